// round 1
// baseline (speedup 1.0000x reference)
#include <cuda_runtime.h>
#include <math.h>

// Problem constants (fixed by the dataset)
#define BATCH 4
#define SEQ   2048
#define DIM   512
#define UDIM  256

// GEMM tiling
#define BM 128
#define BN 128
#define BKK 16

// Scratch (device globals — no cudaMalloc allowed)
__device__ float g_q[(size_t)BATCH * SEQ * UDIM];
__device__ float g_k[(size_t)BATCH * SEQ * UDIM];
__device__ float g_v[(size_t)BATCH * SEQ * UDIM];
__device__ float g_s[(size_t)BATCH * SEQ * SEQ];

// ---------------------------------------------------------------------------
// SGEMM NN: C[M,N] = A[M,K] * B[K,N], all row-major. Batched via blockIdx.z.
// 128x128 tile, BK=16, 256 threads, 8x8 per thread.
// ---------------------------------------------------------------------------
__global__ __launch_bounds__(256)
void sgemm_nn(const float* __restrict__ A, const float* __restrict__ B,
              float* __restrict__ C, int M, int N, int K,
              size_t sA, size_t sB, size_t sC)
{
    A += (size_t)blockIdx.z * sA;
    B += (size_t)blockIdx.z * sB;
    C += (size_t)blockIdx.z * sC;

    __shared__ float As[BKK][BM + 4];   // transposed A tile, padded vs bank conflicts
    __shared__ float Bs[BKK][BN];

    const int tid = threadIdx.x;
    const int tr  = tid >> 4;   // 0..15
    const int tc  = tid & 15;   // 0..15
    const int rowBase = blockIdx.y * BM;
    const int colBase = blockIdx.x * BN;

    float acc[8][8];
    #pragma unroll
    for (int i = 0; i < 8; i++)
        #pragma unroll
        for (int j = 0; j < 8; j++) acc[i][j] = 0.f;

    for (int kk = 0; kk < K; kk += BKK) {
        // Load A tile: 128x16 = 512 float4, 2 per thread, store transposed
        #pragma unroll
        for (int t = 0; t < 2; t++) {
            int i  = tid + t * 256;       // 0..511
            int r  = i >> 2;              // 0..127
            int k4 = (i & 3) * 4;         // 0,4,8,12
            float4 v = *(const float4*)&A[(size_t)(rowBase + r) * K + kk + k4];
            As[k4 + 0][r] = v.x;
            As[k4 + 1][r] = v.y;
            As[k4 + 2][r] = v.z;
            As[k4 + 3][r] = v.w;
        }
        // Load B tile: 16x128 = 512 float4, row-major
        #pragma unroll
        for (int t = 0; t < 2; t++) {
            int i  = tid + t * 256;
            int k  = i >> 5;              // 0..15
            int c4 = (i & 31) * 4;        // 0..124
            float4 v = *(const float4*)&B[(size_t)(kk + k) * N + colBase + c4];
            *(float4*)&Bs[k][c4] = v;
        }
        __syncthreads();

        #pragma unroll
        for (int k = 0; k < BKK; k++) {
            float ra[8], rb[8];
            #pragma unroll
            for (int i = 0; i < 8; i++) ra[i] = As[k][tr * 8 + i];
            #pragma unroll
            for (int j = 0; j < 8; j++) rb[j] = Bs[k][tc * 8 + j];
            #pragma unroll
            for (int i = 0; i < 8; i++)
                #pragma unroll
                for (int j = 0; j < 8; j++)
                    acc[i][j] = fmaf(ra[i], rb[j], acc[i][j]);
        }
        __syncthreads();
    }

    #pragma unroll
    for (int i = 0; i < 8; i++) {
        size_t r = (size_t)(rowBase + tr * 8 + i);
        #pragma unroll
        for (int j4 = 0; j4 < 8; j4 += 4) {
            float4 v = make_float4(acc[i][j4], acc[i][j4+1], acc[i][j4+2], acc[i][j4+3]);
            *(float4*)&C[r * N + colBase + tc * 8 + j4] = v;
        }
    }
}

// ---------------------------------------------------------------------------
// SGEMM NT: C[M,N] = A[M,K] * B^T where B is [N,K] row-major (scores = Q K^T)
// ---------------------------------------------------------------------------
__global__ __launch_bounds__(256)
void sgemm_nt(const float* __restrict__ A, const float* __restrict__ B,
              float* __restrict__ C, int M, int N, int K,
              size_t sA, size_t sB, size_t sC)
{
    A += (size_t)blockIdx.z * sA;
    B += (size_t)blockIdx.z * sB;
    C += (size_t)blockIdx.z * sC;

    __shared__ float As[BKK][BM + 4];
    __shared__ float Bs[BKK][BN + 4];

    const int tid = threadIdx.x;
    const int tr  = tid >> 4;
    const int tc  = tid & 15;
    const int rowBase = blockIdx.y * BM;
    const int colBase = blockIdx.x * BN;

    float acc[8][8];
    #pragma unroll
    for (int i = 0; i < 8; i++)
        #pragma unroll
        for (int j = 0; j < 8; j++) acc[i][j] = 0.f;

    for (int kk = 0; kk < K; kk += BKK) {
        #pragma unroll
        for (int t = 0; t < 2; t++) {
            int i  = tid + t * 256;
            int r  = i >> 2;
            int k4 = (i & 3) * 4;
            float4 v = *(const float4*)&A[(size_t)(rowBase + r) * K + kk + k4];
            As[k4 + 0][r] = v.x;
            As[k4 + 1][r] = v.y;
            As[k4 + 2][r] = v.z;
            As[k4 + 3][r] = v.w;
        }
        // B is [N,K]: tile rows are N, contiguous in K -> load like A, transposed
        #pragma unroll
        for (int t = 0; t < 2; t++) {
            int i  = tid + t * 256;
            int n  = i >> 2;              // 0..127
            int k4 = (i & 3) * 4;
            float4 v = *(const float4*)&B[(size_t)(colBase + n) * K + kk + k4];
            Bs[k4 + 0][n] = v.x;
            Bs[k4 + 1][n] = v.y;
            Bs[k4 + 2][n] = v.z;
            Bs[k4 + 3][n] = v.w;
        }
        __syncthreads();

        #pragma unroll
        for (int k = 0; k < BKK; k++) {
            float ra[8], rb[8];
            #pragma unroll
            for (int i = 0; i < 8; i++) ra[i] = As[k][tr * 8 + i];
            #pragma unroll
            for (int j = 0; j < 8; j++) rb[j] = Bs[k][tc * 8 + j];
            #pragma unroll
            for (int i = 0; i < 8; i++)
                #pragma unroll
                for (int j = 0; j < 8; j++)
                    acc[i][j] = fmaf(ra[i], rb[j], acc[i][j]);
        }
        __syncthreads();
    }

    #pragma unroll
    for (int i = 0; i < 8; i++) {
        size_t r = (size_t)(rowBase + tr * 8 + i);
        #pragma unroll
        for (int j4 = 0; j4 < 8; j4 += 4) {
            float4 v = make_float4(acc[i][j4], acc[i][j4+1], acc[i][j4+2], acc[i][j4+3]);
            *(float4*)&C[r * N + colBase + tc * 8 + j4] = v;
        }
    }
}

// ---------------------------------------------------------------------------
// Row softmax over last dim (n = SEQ). One block (256 threads) per row.
// ---------------------------------------------------------------------------
__global__ __launch_bounds__(256)
void softmax_rows(float* __restrict__ S, int n)
{
    float* row = S + (size_t)blockIdx.x * n;
    const int tid = threadIdx.x;
    __shared__ float red[8];

    // 1) row max
    float m = -INFINITY;
    for (int i = tid; i < n; i += 256) m = fmaxf(m, row[i]);
    #pragma unroll
    for (int o = 16; o > 0; o >>= 1) m = fmaxf(m, __shfl_xor_sync(0xffffffffu, m, o));
    if ((tid & 31) == 0) red[tid >> 5] = m;
    __syncthreads();
    m = red[0];
    #pragma unroll
    for (int i = 1; i < 8; i++) m = fmaxf(m, red[i]);
    __syncthreads();

    // 2) exp + sum
    float s = 0.f;
    for (int i = tid; i < n; i += 256) {
        float e = expf(row[i] - m);
        row[i] = e;
        s += e;
    }
    #pragma unroll
    for (int o = 16; o > 0; o >>= 1) s += __shfl_xor_sync(0xffffffffu, s, o);
    if ((tid & 31) == 0) red[tid >> 5] = s;
    __syncthreads();
    float tot = 0.f;
    #pragma unroll
    for (int i = 0; i < 8; i++) tot += red[i];

    // 3) normalize
    float inv = 1.f / tot;
    for (int i = tid; i < n; i += 256) row[i] *= inv;
}

// ---------------------------------------------------------------------------
// Launch
// ---------------------------------------------------------------------------
extern "C" void kernel_launch(void* const* d_in, const int* in_sizes, int n_in,
                              void* d_out, int out_size)
{
    const float* x  = (const float*)d_in[0];
    const float* Wq = (const float*)d_in[1];
    const float* Wk = (const float*)d_in[2];
    const float* Wv = (const float*)d_in[3];
    float* out = (float*)d_out;

    float *q, *k, *v, *s;
    cudaGetSymbolAddress((void**)&q, g_q);
    cudaGetSymbolAddress((void**)&k, g_k);
    cudaGetSymbolAddress((void**)&v, g_v);
    cudaGetSymbolAddress((void**)&s, g_s);

    dim3 blk(256);

    // 1) QKV projections: [B*S, D] @ [D, U] -> [B*S, U]
    {
        dim3 grid(UDIM / BN, (BATCH * SEQ) / BM, 1);   // (2, 64, 1)
        sgemm_nn<<<grid, blk>>>(x, Wq, q, BATCH * SEQ, UDIM, DIM, 0, 0, 0);
        sgemm_nn<<<grid, blk>>>(x, Wk, k, BATCH * SEQ, UDIM, DIM, 0, 0, 0);
        sgemm_nn<<<grid, blk>>>(x, Wv, v, BATCH * SEQ, UDIM, DIM, 0, 0, 0);
    }

    // 2) scores = Q @ K^T per batch: [S,U] @ [S,U]^T -> [S,S]
    {
        dim3 grid(SEQ / BN, SEQ / BM, BATCH);          // (16, 16, 4)
        sgemm_nt<<<grid, blk>>>(q, k, s, SEQ, SEQ, UDIM,
                                (size_t)SEQ * UDIM, (size_t)SEQ * UDIM,
                                (size_t)SEQ * SEQ);
    }

    // 3) softmax over rows
    {
        dim3 grid(BATCH * SEQ);                         // 8192 rows
        softmax_rows<<<grid, blk>>>(s, SEQ);
    }

    // 4) out = P @ V per batch: [S,S] @ [S,U] -> [S,U]
    {
        dim3 grid(UDIM / BN, SEQ / BM, BATCH);          // (2, 16, 4)
        sgemm_nn<<<grid, blk>>>(s, v, out, SEQ, UDIM, SEQ,
                                (size_t)SEQ * SEQ, (size_t)SEQ * UDIM,
                                (size_t)SEQ * UDIM);
    }
}

// round 3
// speedup vs baseline: 2.2151x; 2.2151x over previous
#include <cuda_runtime.h>
#include <cuda_bf16.h>
#include <math.h>
#include <stdint.h>

#define BATCH 4
#define SEQ   2048
#define DIM   512
#define UDIM  256

// ---------------- scratch (device globals; no cudaMalloc allowed) ----------
__device__ float g_q [(size_t)BATCH*SEQ*UDIM];
__device__ float g_k [(size_t)BATCH*SEQ*UDIM];
__device__ float g_v [(size_t)BATCH*SEQ*UDIM];
__device__ float g_s [(size_t)BATCH*SEQ*SEQ];
__device__ float g_wt[(size_t)3*UDIM*DIM];
__device__ float g_vt[(size_t)BATCH*UDIM*SEQ];

// ---------------- helpers ----------------------------------------------------
__device__ __forceinline__ uint32_t smem_u32(const void* p){
    uint32_t a;
    asm("{ .reg .u64 t; cvta.to.shared.u64 t, %1; cvt.u32.u64 %0, t; }" : "=r"(a) : "l"(p));
    return a;
}
__device__ __forceinline__ uint32_t sw128(uint32_t off){ return off ^ ((off>>3)&0x70); }

__device__ __forceinline__ uint32_t packbf(__nv_bfloat16 a, __nv_bfloat16 b){
    __nv_bfloat162 t; t.x = a; t.y = b;
    return *reinterpret_cast<uint32_t*>(&t);
}
__device__ __forceinline__ void split4(float4 v, uint2& hi, uint2& lo){
    __nv_bfloat16 hx = __float2bfloat16(v.x);
    __nv_bfloat16 hy = __float2bfloat16(v.y);
    __nv_bfloat16 hz = __float2bfloat16(v.z);
    __nv_bfloat16 hw = __float2bfloat16(v.w);
    __nv_bfloat16 lx = __float2bfloat16(v.x - __bfloat162float(hx));
    __nv_bfloat16 ly = __float2bfloat16(v.y - __bfloat162float(hy));
    __nv_bfloat16 lz = __float2bfloat16(v.z - __bfloat162float(hz));
    __nv_bfloat16 lw = __float2bfloat16(v.w - __bfloat162float(hw));
    hi.x = packbf(hx, hy);  hi.y = packbf(hz, hw);
    lo.x = packbf(lx, ly);  lo.y = packbf(lz, lw);
}

__device__ __forceinline__ void ldm_x4(uint32_t* r, uint32_t addr){
    asm volatile("ldmatrix.sync.aligned.m8n8.x4.shared.b16 {%0,%1,%2,%3}, [%4];"
                 : "=r"(r[0]), "=r"(r[1]), "=r"(r[2]), "=r"(r[3]) : "r"(addr));
}
#define MMA16816(d, a, b0v, b1v) \
    asm volatile("mma.sync.aligned.m16n8k16.row.col.f32.bf16.bf16.f32 " \
                 "{%0,%1,%2,%3},{%4,%5,%6,%7},{%8,%9},{%0,%1,%2,%3};" \
                 : "+f"((d)[0]), "+f"((d)[1]), "+f"((d)[2]), "+f"((d)[3]) \
                 : "r"((a)[0]), "r"((a)[1]), "r"((a)[2]), "r"((a)[3]), \
                   "r"(b0v), "r"(b1v))

// ---------------- bf16x3 NT GEMM via mma.sync -------------------------------
// C[M,N] = A[M,K] * B[N,K]^T, fp32 in/out. CTA tile 128x128, K-chunk 32.
// smem tile row layout: 128 bytes = [32 bf16 hi | 32 bf16 lo], XOR-swizzled.
#define TILE_BYTES 16384                 // 128 rows * 128B
#define GSMEM (4*TILE_BYTES)             // A0,B0,A1,B1

__global__ __launch_bounds__(256)
void gemm_nt_bf16x3(const float* __restrict__ A, const float* __restrict__ B,
                    float* __restrict__ C, int K, int ldA, int ldB, int ldC,
                    size_t sA, size_t sB, size_t sC)
{
    extern __shared__ char smem[];
    A += (size_t)blockIdx.z * sA;
    B += (size_t)blockIdx.z * sB;
    C += (size_t)blockIdx.z * sC;

    char* bufA[2] = { smem,                  smem + 2*TILE_BYTES };
    char* bufB[2] = { smem + TILE_BYTES,     smem + 3*TILE_BYTES };

    const int tid = threadIdx.x;
    const int wid = tid >> 5;
    const int lt  = tid & 31;
    const int warpM = (wid & 1) * 64;
    const int warpN = (wid >> 1) * 32;

    const int rowBase = blockIdx.y * 128;
    const int colBase = blockIdx.x * 128;

    // global staging: thread -> row tid/2, k-half tid&1 (16 floats = 4 float4)
    const int gr = tid >> 1;
    const int kh = tid & 1;
    const float4* gA = (const float4*)(A + (size_t)(rowBase + gr) * ldA) + kh*4;
    const float4* gB = (const float4*)(B + (size_t)(colBase + gr) * ldB) + kh*4;
    const uint32_t stRow = (uint32_t)gr * 128;
    const uint32_t stCol = (uint32_t)kh * 32;

    // fragment smem base offsets (per-thread, before swizzle)
    // A: row = lt&15 within 16-row tile, 16B-granule = lt>>4
    const uint32_t aFragOff = (uint32_t)((warpM + (lt & 15)) * 128 + ((lt >> 4) & 1) * 16);
    // B: row = (lt&7) + ((lt>>4)&1)*8, granule = (lt>>3)&1
    const uint32_t bFragOff = (uint32_t)((warpN + (lt & 7) + ((lt >> 4) & 1) * 8) * 128
                                         + ((lt >> 3) & 1) * 16);

    float acc[4][4][4];
    #pragma unroll
    for (int i = 0; i < 4; i++)
        #pragma unroll
        for (int j = 0; j < 4; j++)
            #pragma unroll
            for (int e = 0; e < 4; e++) acc[i][j][e] = 0.f;

    const int nch = K / 32;
    float4 va[4], vb[4];

    // ---- prologue: chunk 0 -> smem buf0; chunk 1 -> regs ----
    #pragma unroll
    for (int j = 0; j < 4; j++) va[j] = gA[j];
    #pragma unroll
    for (int j = 0; j < 4; j++) vb[j] = gB[j];
    #pragma unroll
    for (int j = 0; j < 4; j++) {
        uint2 hi, lo;
        uint32_t co = stCol + (uint32_t)j * 8;
        split4(va[j], hi, lo);
        *(uint2*)(bufA[0] + sw128(stRow + co))      = hi;
        *(uint2*)(bufA[0] + sw128(stRow + 64 + co)) = lo;
        split4(vb[j], hi, lo);
        *(uint2*)(bufB[0] + sw128(stRow + co))      = hi;
        *(uint2*)(bufB[0] + sw128(stRow + 64 + co)) = lo;
    }
    if (nch > 1) {
        #pragma unroll
        for (int j = 0; j < 4; j++) va[j] = gA[8 + j];
        #pragma unroll
        for (int j = 0; j < 4; j++) vb[j] = gB[8 + j];
    }
    __syncthreads();

    for (int c = 0; c < nch; c++) {
        const int buf = c & 1;
        const uint32_t aBase = smem_u32(bufA[buf]);
        const uint32_t bBase = smem_u32(bufB[buf]);

        // ---- compute chunk c: two k16 steps ----
        #pragma unroll
        for (int s = 0; s < 2; s++) {
            uint32_t ah[4][4], al[4][4], bh[2][4], bl[2][4];
            #pragma unroll
            for (int mt = 0; mt < 4; mt++) {
                uint32_t o = aFragOff + (uint32_t)mt * 16 * 128 + (uint32_t)s * 32;
                ldm_x4(ah[mt], aBase + sw128(o));
                ldm_x4(al[mt], aBase + sw128(o + 64));
            }
            #pragma unroll
            for (int np = 0; np < 2; np++) {
                uint32_t o = bFragOff + (uint32_t)np * 16 * 128 + (uint32_t)s * 32;
                ldm_x4(bh[np], bBase + sw128(o));
                ldm_x4(bl[np], bBase + sw128(o + 64));
            }
            #pragma unroll
            for (int mt = 0; mt < 4; mt++) {
                #pragma unroll
                for (int nt = 0; nt < 4; nt++) {
                    const int np = nt >> 1, ix = (nt & 1) * 2;
                    MMA16816(acc[mt][nt], ah[mt], bh[np][ix], bh[np][ix+1]);
                    MMA16816(acc[mt][nt], ah[mt], bl[np][ix], bl[np][ix+1]);
                    MMA16816(acc[mt][nt], al[mt], bh[np][ix], bh[np][ix+1]);
                }
            }
        }

        // ---- store staged chunk c+1, prefetch chunk c+2 ----
        if (c + 1 < nch) {
            char* dA = bufA[(c + 1) & 1];
            char* dB = bufB[(c + 1) & 1];
            #pragma unroll
            for (int j = 0; j < 4; j++) {
                uint2 hi, lo;
                uint32_t co = stCol + (uint32_t)j * 8;
                split4(va[j], hi, lo);
                *(uint2*)(dA + sw128(stRow + co))      = hi;
                *(uint2*)(dA + sw128(stRow + 64 + co)) = lo;
                split4(vb[j], hi, lo);
                *(uint2*)(dB + sw128(stRow + co))      = hi;
                *(uint2*)(dB + sw128(stRow + 64 + co)) = lo;
            }
            if (c + 2 < nch) {
                const float4* pa = gA + (size_t)(c + 2) * 8;
                const float4* pb = gB + (size_t)(c + 2) * 8;
                #pragma unroll
                for (int j = 0; j < 4; j++) va[j] = pa[j];
                #pragma unroll
                for (int j = 0; j < 4; j++) vb[j] = pb[j];
            }
        }
        __syncthreads();
    }

    // ---- epilogue: fp32 direct to global ----
    #pragma unroll
    for (int mt = 0; mt < 4; mt++) {
        const int r0 = rowBase + warpM + mt * 16 + (lt >> 2);
        #pragma unroll
        for (int nt = 0; nt < 4; nt++) {
            const int cc = colBase + warpN + nt * 8 + (lt & 3) * 2;
            float2 v0 = make_float2(acc[mt][nt][0], acc[mt][nt][1]);
            float2 v1 = make_float2(acc[mt][nt][2], acc[mt][nt][3]);
            *(float2*)&C[(size_t)r0 * ldC + cc]       = v0;
            *(float2*)&C[(size_t)(r0 + 8) * ldC + cc] = v1;
        }
    }
}

// ---------------- transpose [R,C] -> [C,R] ---------------------------------
__global__ __launch_bounds__(256)
void transpose32(const float* __restrict__ in, float* __restrict__ out,
                 int R, int C, size_t sIn, size_t sOut)
{
    __shared__ float t[32][33];
    in  += (size_t)blockIdx.z * sIn;
    out += (size_t)blockIdx.z * sOut;
    int x = blockIdx.x * 32 + threadIdx.x;
    int y = blockIdx.y * 32 + threadIdx.y;
    #pragma unroll
    for (int j = 0; j < 32; j += 8)
        t[threadIdx.y + j][threadIdx.x] = in[(size_t)(y + j) * C + x];
    __syncthreads();
    x = blockIdx.y * 32 + threadIdx.x;
    y = blockIdx.x * 32 + threadIdx.y;
    #pragma unroll
    for (int j = 0; j < 32; j += 8)
        out[(size_t)(y + j) * R + x] = t[threadIdx.x][threadIdx.y + j];
}

// ---------------- register-resident row softmax (SEQ=2048) -----------------
__global__ __launch_bounds__(256)
void softmax_row(float* __restrict__ S)
{
    float4* row = (float4*)(S + (size_t)blockIdx.x * SEQ);
    const int tid = threadIdx.x;
    __shared__ float red[8];

    float4 a = row[tid];
    float4 b = row[tid + 256];

    float m = fmaxf(fmaxf(fmaxf(a.x, a.y), fmaxf(a.z, a.w)),
                    fmaxf(fmaxf(b.x, b.y), fmaxf(b.z, b.w)));
    #pragma unroll
    for (int o = 16; o > 0; o >>= 1) m = fmaxf(m, __shfl_xor_sync(0xffffffffu, m, o));
    if ((tid & 31) == 0) red[tid >> 5] = m;
    __syncthreads();
    m = red[0];
    #pragma unroll
    for (int i = 1; i < 8; i++) m = fmaxf(m, red[i]);
    __syncthreads();

    a.x = __expf(a.x - m); a.y = __expf(a.y - m); a.z = __expf(a.z - m); a.w = __expf(a.w - m);
    b.x = __expf(b.x - m); b.y = __expf(b.y - m); b.z = __expf(b.z - m); b.w = __expf(b.w - m);
    float s = (a.x + a.y) + (a.z + a.w) + (b.x + b.y) + (b.z + b.w);
    #pragma unroll
    for (int o = 16; o > 0; o >>= 1) s += __shfl_xor_sync(0xffffffffu, s, o);
    if ((tid & 31) == 0) red[tid >> 5] = s;
    __syncthreads();
    float tot = 0.f;
    #pragma unroll
    for (int i = 0; i < 8; i++) tot += red[i];

    float inv = 1.f / tot;
    a.x *= inv; a.y *= inv; a.z *= inv; a.w *= inv;
    b.x *= inv; b.y *= inv; b.z *= inv; b.w *= inv;
    row[tid]       = a;
    row[tid + 256] = b;
}

// ---------------- launch ----------------------------------------------------
extern "C" void kernel_launch(void* const* d_in, const int* in_sizes, int n_in,
                              void* d_out, int out_size)
{
    const float* x  = (const float*)d_in[0];
    const float* Wq = (const float*)d_in[1];
    const float* Wk = (const float*)d_in[2];
    const float* Wv = (const float*)d_in[3];
    float* out = (float*)d_out;

    float *q, *k, *v, *s, *wt, *vt;
    cudaGetSymbolAddress((void**)&q,  g_q);
    cudaGetSymbolAddress((void**)&k,  g_k);
    cudaGetSymbolAddress((void**)&v,  g_v);
    cudaGetSymbolAddress((void**)&s,  g_s);
    cudaGetSymbolAddress((void**)&wt, g_wt);
    cudaGetSymbolAddress((void**)&vt, g_vt);

    cudaFuncSetAttribute(gemm_nt_bf16x3,
                         cudaFuncAttributeMaxDynamicSharedMemorySize, GSMEM);

    const size_t WSZ = (size_t)UDIM * DIM;
    dim3 tb(32, 8);

    // 1) transpose weights: [D,U] -> [U,D]
    transpose32<<<dim3(UDIM/32, DIM/32, 1), tb>>>(Wq, wt + 0*WSZ, DIM, UDIM, 0, 0);
    transpose32<<<dim3(UDIM/32, DIM/32, 1), tb>>>(Wk, wt + 1*WSZ, DIM, UDIM, 0, 0);
    transpose32<<<dim3(UDIM/32, DIM/32, 1), tb>>>(Wv, wt + 2*WSZ, DIM, UDIM, 0, 0);

    // 2) QKV projections: [8192,512] x [256,512]^T -> [8192,256]
    {
        dim3 grid(UDIM/128, (BATCH*SEQ)/128, 1);
        gemm_nt_bf16x3<<<grid, 256, GSMEM>>>(x, wt + 0*WSZ, q, DIM, DIM, DIM, UDIM, 0, 0, 0);
        gemm_nt_bf16x3<<<grid, 256, GSMEM>>>(x, wt + 1*WSZ, k, DIM, DIM, DIM, UDIM, 0, 0, 0);
        gemm_nt_bf16x3<<<grid, 256, GSMEM>>>(x, wt + 2*WSZ, v, DIM, DIM, DIM, UDIM, 0, 0, 0);
    }

    // 3) transpose V per batch: [S,U] -> [U,S]
    transpose32<<<dim3(UDIM/32, SEQ/32, BATCH), tb>>>(v, vt, SEQ, UDIM,
                                                      (size_t)SEQ*UDIM, (size_t)UDIM*SEQ);

    // 4) scores = Q K^T per batch
    {
        dim3 grid(SEQ/128, SEQ/128, BATCH);
        gemm_nt_bf16x3<<<grid, 256, GSMEM>>>(q, k, s, UDIM, UDIM, UDIM, SEQ,
                                             (size_t)SEQ*UDIM, (size_t)SEQ*UDIM,
                                             (size_t)SEQ*SEQ);
    }

    // 5) softmax rows
    softmax_row<<<BATCH*SEQ, 256>>>(s);

    // 6) out = P V per batch: [2048,2048] x [256,2048]^T -> [2048,256]
    {
        dim3 grid(UDIM/128, SEQ/128, BATCH);
        gemm_nt_bf16x3<<<grid, 256, GSMEM>>>(s, vt, out, SEQ, SEQ, SEQ, UDIM,
                                             (size_t)SEQ*SEQ, (size_t)UDIM*SEQ,
                                             (size_t)SEQ*UDIM);
    }
}

// round 4
// speedup vs baseline: 2.9265x; 1.3212x over previous
#include <cuda_runtime.h>
#include <cuda_bf16.h>
#include <math.h>
#include <stdint.h>

#define BATCH 4
#define SEQ   2048
#define DIM   512
#define UDIM  256
#define MROWS (BATCH*SEQ)

// ---------------- scratch (device globals) ---------------------------------
// packed-split bf16 format: row-major, per 32-k chunk 128 bytes = [32 bf16 hi][32 bf16 lo]
__device__ __align__(128) unsigned char g_xps [(size_t)MROWS*DIM*4];
__device__ __align__(128) unsigned char g_wps [(size_t)3*UDIM*DIM*4];
__device__ __align__(128) unsigned char g_qps [(size_t)MROWS*UDIM*4];
__device__ __align__(128) unsigned char g_kps [(size_t)MROWS*UDIM*4];
__device__ __align__(128) float         g_v   [(size_t)MROWS*UDIM];
__device__ __align__(128) unsigned char g_vtps[(size_t)BATCH*UDIM*SEQ*4];
__device__ __align__(128) float         g_s   [(size_t)BATCH*SEQ*SEQ];
__device__ __align__(128) unsigned char g_pps [(size_t)BATCH*SEQ*SEQ*4];

// ---------------- helpers ---------------------------------------------------
__device__ __forceinline__ uint32_t smem_u32(const void* p){
    uint32_t a;
    asm("{ .reg .u64 t; cvta.to.shared.u64 t, %1; cvt.u32.u64 %0, t; }" : "=r"(a) : "l"(p));
    return a;
}
__device__ __forceinline__ uint32_t sw128(uint32_t off){ return off ^ ((off>>3)&0x70); }

__device__ __forceinline__ uint32_t packbf(__nv_bfloat16 a, __nv_bfloat16 b){
    __nv_bfloat162 t; t.x = a; t.y = b;
    return *reinterpret_cast<uint32_t*>(&t);
}
__device__ __forceinline__ void split2(float a, float b, uint32_t& hi, uint32_t& lo){
    __nv_bfloat16 ha = __float2bfloat16(a), hb = __float2bfloat16(b);
    hi = packbf(ha, hb);
    lo = packbf(__float2bfloat16(a - __bfloat162float(ha)),
                __float2bfloat16(b - __bfloat162float(hb)));
}
__device__ __forceinline__ void split4(float4 v, uint2& hi, uint2& lo){
    split2(v.x, v.y, hi.x, lo.x);
    split2(v.z, v.w, hi.y, lo.y);
}

__device__ __forceinline__ void cpa16(uint32_t dst, const void* src){
    asm volatile("cp.async.cg.shared.global [%0], [%1], 16;" :: "r"(dst), "l"(src));
}
__device__ __forceinline__ void cpa_commit(){ asm volatile("cp.async.commit_group;" ::: "memory"); }
template<int N> __device__ __forceinline__ void cpa_wait(){
    asm volatile("cp.async.wait_group %0;" :: "n"(N) : "memory");
}
__device__ __forceinline__ void ldm_x4(uint32_t* r, uint32_t addr){
    asm volatile("ldmatrix.sync.aligned.m8n8.x4.shared.b16 {%0,%1,%2,%3}, [%4];"
                 : "=r"(r[0]), "=r"(r[1]), "=r"(r[2]), "=r"(r[3]) : "r"(addr));
}
#define MMA16816(d, a, b0v, b1v) \
    asm volatile("mma.sync.aligned.m16n8k16.row.col.f32.bf16.bf16.f32 " \
                 "{%0,%1,%2,%3},{%4,%5,%6,%7},{%8,%9},{%0,%1,%2,%3};" \
                 : "+f"((d)[0]), "+f"((d)[1]), "+f"((d)[2]), "+f"((d)[3]) \
                 : "r"((a)[0]), "r"((a)[1]), "r"((a)[2]), "r"((a)[3]), \
                   "r"(b0v), "r"(b1v))

// ---------------- bf16x3 NT GEMM on packed-split operands ------------------
// C[M,N] = A[M,K] * B[N,K]^T. CTA 128x128, 512 thr, warp tile 32x32,
// K-chunk 32, 4-stage cp.async pipeline.
#define STAGES    4
#define STG_BYTES 16384
#define SMEM_GEMM (STAGES*2*STG_BYTES)   // 128 KB

template<int OUT_PS>
__global__ __launch_bounds__(512)
void gemm_ps(const unsigned char* __restrict__ A, const unsigned char* __restrict__ B,
             float* __restrict__ Cf, unsigned char* __restrict__ Cp,
             int K, int pitchA, int pitchB, int ldC,
             size_t sA, size_t sB, size_t sC)
{
    extern __shared__ char smem[];
    A += (size_t)blockIdx.z * sA;
    B += (size_t)blockIdx.z * sB;

    const int tid = threadIdx.x;
    const int wid = tid >> 5, lt = tid & 31;
    const int warpM = (wid & 3) * 32, warpN = (wid >> 2) * 32;
    const int rowBase = blockIdx.y * 128, colBase = blockIdx.x * 128;

    // cp.async mapping: thread -> row lr, 32B segment lg
    const int lr = tid >> 2;
    const int lg = (tid & 3) * 32;
    const uint32_t mask = (uint32_t)(lr & 7) * 16;
    const uint32_t o1 = (uint32_t)lr * 128 + ((uint32_t)lg ^ mask);
    const uint32_t o2 = o1 ^ 16;
    const unsigned char* gA = A + (size_t)(rowBase + lr) * pitchA + lg;
    const unsigned char* gB = B + (size_t)(colBase + lr) * pitchB + lg;

    const uint32_t sb = smem_u32(smem);
    const int nch = K / 32;

    // fragment raw offsets (swizzle applied at use)
    const uint32_t aOff = (uint32_t)((warpM + (lt & 15)) * 128 + ((lt >> 4) & 1) * 16);
    const uint32_t bOff = (uint32_t)((warpN + (lt & 7) + ((lt >> 4) & 1) * 8) * 128
                                     + ((lt >> 3) & 1) * 16);

    float acc[2][4][4];
    #pragma unroll
    for (int i = 0; i < 2; i++)
        #pragma unroll
        for (int j = 0; j < 4; j++)
            #pragma unroll
            for (int e = 0; e < 4; e++) acc[i][j][e] = 0.f;

    // prologue: stages 0..2
    #pragma unroll
    for (int st = 0; st < 3; st++) {
        uint32_t base = sb + (uint32_t)st * (2*STG_BYTES);
        const unsigned char* pa = gA + (size_t)st * 128;
        const unsigned char* pb = gB + (size_t)st * 128;
        cpa16(base + o1, pa);                 cpa16(base + o2, pa + 16);
        cpa16(base + STG_BYTES + o1, pb);     cpa16(base + STG_BYTES + o2, pb + 16);
        cpa_commit();
    }

    for (int c = 0; c < nch; c++) {
        cpa_wait<2>();
        __syncthreads();

        if (c + 3 < nch) {
            uint32_t base = sb + (uint32_t)((c + 3) & 3) * (2*STG_BYTES);
            const unsigned char* pa = gA + (size_t)(c + 3) * 128;
            const unsigned char* pb = gB + (size_t)(c + 3) * 128;
            cpa16(base + o1, pa);                 cpa16(base + o2, pa + 16);
            cpa16(base + STG_BYTES + o1, pb);     cpa16(base + STG_BYTES + o2, pb + 16);
        }
        cpa_commit();

        const uint32_t aB = sb + (uint32_t)(c & 3) * (2*STG_BYTES);
        const uint32_t bB = aB + STG_BYTES;

        #pragma unroll
        for (int s = 0; s < 2; s++) {
            uint32_t ah[2][4], al[2][4], bh[2][4], bl[2][4];
            #pragma unroll
            for (int mt = 0; mt < 2; mt++) {
                uint32_t o = aOff + (uint32_t)mt * 2048 + (uint32_t)s * 32;
                ldm_x4(ah[mt], aB + sw128(o));
                ldm_x4(al[mt], aB + sw128(o + 64));
            }
            #pragma unroll
            for (int np = 0; np < 2; np++) {
                uint32_t o = bOff + (uint32_t)np * 2048 + (uint32_t)s * 32;
                ldm_x4(bh[np], bB + sw128(o));
                ldm_x4(bl[np], bB + sw128(o + 64));
            }
            #pragma unroll
            for (int mt = 0; mt < 2; mt++) {
                #pragma unroll
                for (int nt = 0; nt < 4; nt++) {
                    const int np = nt >> 1, ix = (nt & 1) * 2;
                    MMA16816(acc[mt][nt], ah[mt], bh[np][ix], bh[np][ix+1]);
                    MMA16816(acc[mt][nt], ah[mt], bl[np][ix], bl[np][ix+1]);
                    MMA16816(acc[mt][nt], al[mt], bh[np][ix], bh[np][ix+1]);
                }
            }
        }
    }

    // ---- epilogue ----
    if (OUT_PS) {
        unsigned char* O = Cp + (size_t)blockIdx.z * sC;
        #pragma unroll
        for (int mt = 0; mt < 2; mt++) {
            const int r0 = rowBase + warpM + mt * 16 + (lt >> 2);
            #pragma unroll
            for (int nt = 0; nt < 4; nt++) {
                const int col = colBase + warpN + nt * 8 + (lt & 3) * 2;
                const uint32_t cb = (uint32_t)(col >> 5) * 128 + (uint32_t)(col & 31) * 2;
                uint32_t hi, lo;
                split2(acc[mt][nt][0], acc[mt][nt][1], hi, lo);
                unsigned char* p0 = O + (size_t)r0 * ldC + cb;
                *(uint32_t*)p0        = hi;
                *(uint32_t*)(p0 + 64) = lo;
                split2(acc[mt][nt][2], acc[mt][nt][3], hi, lo);
                unsigned char* p1 = O + (size_t)(r0 + 8) * ldC + cb;
                *(uint32_t*)p1        = hi;
                *(uint32_t*)(p1 + 64) = lo;
            }
        }
    } else {
        float* C = Cf + (size_t)blockIdx.z * sC;
        #pragma unroll
        for (int mt = 0; mt < 2; mt++) {
            const int r0 = rowBase + warpM + mt * 16 + (lt >> 2);
            #pragma unroll
            for (int nt = 0; nt < 4; nt++) {
                const int cc = colBase + warpN + nt * 8 + (lt & 3) * 2;
                *(float2*)&C[(size_t)r0 * ldC + cc] =
                    make_float2(acc[mt][nt][0], acc[mt][nt][1]);
                *(float2*)&C[(size_t)(r0 + 8) * ldC + cc] =
                    make_float2(acc[mt][nt][2], acc[mt][nt][3]);
            }
        }
    }
}

// ---------------- split fp32 -> packed-split (row-major preserved) ---------
__global__ __launch_bounds__(256)
void split_pack(const float* __restrict__ in, unsigned char* __restrict__ out, int Kelems)
{
    const size_t idx = ((size_t)blockIdx.x * 256 + threadIdx.x) * 8;
    const size_t row = idx / Kelems;
    const int k0 = (int)(idx % Kelems);
    float4 f0 = *(const float4*)(in + idx);
    float4 f1 = *(const float4*)(in + idx + 4);
    uint2 h0, l0, h1, l1;
    split4(f0, h0, l0);
    split4(f1, h1, l1);
    unsigned char* p = out + row * ((size_t)Kelems * 4) + (k0 >> 5) * 128 + (k0 & 31) * 2;
    *(uint4*)p        = make_uint4(h0.x, h0.y, h1.x, h1.y);
    *(uint4*)(p + 64) = make_uint4(l0.x, l0.y, l1.x, l1.y);
}

// ---------------- transpose [R,C] fp32 -> packed-split [C rows, R k] --------
__global__ __launch_bounds__(256)
void transpose_split(const float* __restrict__ in, unsigned char* __restrict__ out,
                     int R, int C, size_t sIn, size_t sOut)
{
    __shared__ float t[32][33];
    in  += (size_t)blockIdx.z * sIn;
    out += (size_t)blockIdx.z * sOut;
    const int tid = threadIdx.x;
    const int tx = tid & 31, ty = tid >> 5;
    int x = blockIdx.x * 32 + tx;
    int y = blockIdx.y * 32 + ty;
    #pragma unroll
    for (int j = 0; j < 32; j += 8)
        t[ty + j][tx] = in[(size_t)(y + j) * C + x];
    __syncthreads();

    const int wr = tid >> 3;   // output row within tile (C index)
    const int wg = tid & 7;    // group of 4 along k (R index)
    float f0 = t[wg*4 + 0][wr];
    float f1 = t[wg*4 + 1][wr];
    float f2 = t[wg*4 + 2][wr];
    float f3 = t[wg*4 + 3][wr];
    uint32_t h0, l0, h1, l1;
    split2(f0, f1, h0, l0);
    split2(f2, f3, h1, l1);
    const size_t pitch = (size_t)R * 4;
    unsigned char* p = out + (size_t)(blockIdx.x * 32 + wr) * pitch
                           + (size_t)blockIdx.y * 128 + wg * 8;
    *(uint2*)p        = make_uint2(h0, h1);
    *(uint2*)(p + 64) = make_uint2(l0, l1);
}

// ---------------- softmax + split (SEQ=2048 per row) ------------------------
__global__ __launch_bounds__(256)
void softmax_split(const float* __restrict__ S, unsigned char* __restrict__ P)
{
    const float4* row = (const float4*)(S + (size_t)blockIdx.x * SEQ);
    unsigned char* prow = P + (size_t)blockIdx.x * (SEQ * 4);
    const int tid = threadIdx.x;
    __shared__ float red[8];

    float4 a = row[tid];
    float4 b = row[tid + 256];

    float m = fmaxf(fmaxf(fmaxf(a.x, a.y), fmaxf(a.z, a.w)),
                    fmaxf(fmaxf(b.x, b.y), fmaxf(b.z, b.w)));
    #pragma unroll
    for (int o = 16; o > 0; o >>= 1) m = fmaxf(m, __shfl_xor_sync(0xffffffffu, m, o));
    if ((tid & 31) == 0) red[tid >> 5] = m;
    __syncthreads();
    m = red[0];
    #pragma unroll
    for (int i = 1; i < 8; i++) m = fmaxf(m, red[i]);
    __syncthreads();

    a.x = __expf(a.x - m); a.y = __expf(a.y - m); a.z = __expf(a.z - m); a.w = __expf(a.w - m);
    b.x = __expf(b.x - m); b.y = __expf(b.y - m); b.z = __expf(b.z - m); b.w = __expf(b.w - m);
    float s = (a.x + a.y) + (a.z + a.w) + (b.x + b.y) + (b.z + b.w);
    #pragma unroll
    for (int o = 16; o > 0; o >>= 1) s += __shfl_xor_sync(0xffffffffu, s, o);
    if ((tid & 31) == 0) red[tid >> 5] = s;
    __syncthreads();
    float tot = 0.f;
    #pragma unroll
    for (int i = 0; i < 8; i++) tot += red[i];

    const float inv = 1.f / tot;
    a.x *= inv; a.y *= inv; a.z *= inv; a.w *= inv;
    b.x *= inv; b.y *= inv; b.z *= inv; b.w *= inv;

    uint2 hi, lo;
    int k0 = tid * 4;
    split4(a, hi, lo);
    unsigned char* p = prow + (k0 >> 5) * 128 + (k0 & 31) * 2;
    *(uint2*)p        = hi;
    *(uint2*)(p + 64) = lo;
    k0 += 1024;
    split4(b, hi, lo);
    p = prow + (k0 >> 5) * 128 + (k0 & 31) * 2;
    *(uint2*)p        = hi;
    *(uint2*)(p + 64) = lo;
}

// ---------------- launch ----------------------------------------------------
extern "C" void kernel_launch(void* const* d_in, const int* in_sizes, int n_in,
                              void* d_out, int out_size)
{
    const float* x  = (const float*)d_in[0];
    const float* Wq = (const float*)d_in[1];
    const float* Wk = (const float*)d_in[2];
    const float* Wv = (const float*)d_in[3];
    float* out = (float*)d_out;

    unsigned char *xps, *wps, *qps, *kps, *vtps, *pps;
    float *v, *s;
    cudaGetSymbolAddress((void**)&xps,  g_xps);
    cudaGetSymbolAddress((void**)&wps,  g_wps);
    cudaGetSymbolAddress((void**)&qps,  g_qps);
    cudaGetSymbolAddress((void**)&kps,  g_kps);
    cudaGetSymbolAddress((void**)&v,    g_v);
    cudaGetSymbolAddress((void**)&vtps, g_vtps);
    cudaGetSymbolAddress((void**)&s,    g_s);
    cudaGetSymbolAddress((void**)&pps,  g_pps);

    cudaFuncSetAttribute(gemm_ps<0>, cudaFuncAttributeMaxDynamicSharedMemorySize, SMEM_GEMM);
    cudaFuncSetAttribute(gemm_ps<1>, cudaFuncAttributeMaxDynamicSharedMemorySize, SMEM_GEMM);

    const size_t WPS = (size_t)UDIM * DIM * 4;

    // 1) split x -> xps
    split_pack<<<(MROWS*DIM)/(256*8), 256>>>(x, xps, DIM);

    // 2) weights: transpose+split [D,U] -> ps [U, D]
    transpose_split<<<dim3(UDIM/32, DIM/32, 1), 256>>>(Wq, wps + 0*WPS, DIM, UDIM, 0, 0);
    transpose_split<<<dim3(UDIM/32, DIM/32, 1), 256>>>(Wk, wps + 1*WPS, DIM, UDIM, 0, 0);
    transpose_split<<<dim3(UDIM/32, DIM/32, 1), 256>>>(Wv, wps + 2*WPS, DIM, UDIM, 0, 0);

    // 3) QKV projections (q,k straight to packed-split; v to fp32)
    {
        dim3 g(UDIM/128, MROWS/128, 1);
        gemm_ps<1><<<g, 512, SMEM_GEMM>>>(xps, wps + 0*WPS, nullptr, qps,
                                          DIM, DIM*4, DIM*4, UDIM*4, 0, 0, 0);
        gemm_ps<1><<<g, 512, SMEM_GEMM>>>(xps, wps + 1*WPS, nullptr, kps,
                                          DIM, DIM*4, DIM*4, UDIM*4, 0, 0, 0);
        gemm_ps<0><<<g, 512, SMEM_GEMM>>>(xps, wps + 2*WPS, v, nullptr,
                                          DIM, DIM*4, DIM*4, UDIM, 0, 0, 0);
    }

    // 4) v -> vt packed-split per batch
    transpose_split<<<dim3(UDIM/32, SEQ/32, BATCH), 256>>>(v, vtps, SEQ, UDIM,
        (size_t)SEQ*UDIM, (size_t)UDIM*SEQ*4);

    // 5) scores = Q K^T
    {
        dim3 g(SEQ/128, SEQ/128, BATCH);
        gemm_ps<0><<<g, 512, SMEM_GEMM>>>(qps, kps, s, nullptr,
                                          UDIM, UDIM*4, UDIM*4, SEQ,
                                          (size_t)SEQ*UDIM*4, (size_t)SEQ*UDIM*4,
                                          (size_t)SEQ*SEQ);
    }

    // 6) softmax + split -> pps
    softmax_split<<<BATCH*SEQ, 256>>>(s, pps);

    // 7) out = P V
    {
        dim3 g(UDIM/128, SEQ/128, BATCH);
        gemm_ps<0><<<g, 512, SMEM_GEMM>>>(pps, vtps, out, nullptr,
                                          SEQ, SEQ*4, SEQ*4, UDIM,
                                          (size_t)SEQ*SEQ*4, (size_t)UDIM*SEQ*4,
                                          (size_t)SEQ*UDIM);
    }
}